// round 10
// baseline (speedup 1.0000x reference)
#include <cuda_runtime.h>

#define NNODES 50000
#define NEDGES 500000
#define NGRAPHS 500
#define NPG 100
#define FIN 16
#define SCAN_NBLK ((NNODES + 1 + 1023) / 1024)   // 49
#define EMAX 2048                                 // per-graph edge cap for SMEM staging

// ---------------- scratch (device globals; no allocation allowed) ----------------
__device__ float d_h0[NNODES * FIN];
__device__ float d_hA[NNODES * 256];
__device__ float d_hB[NNODES * 256];
__device__ float d_asrc[NNODES * 4];
__device__ float d_adst[NNODES * 4];
__device__ int   d_off[NNODES + 1];
__device__ int   d_cursor[NNODES];
__device__ int   d_srcs[NEDGES];
__device__ int   d_bsum[64];
__device__ float d_pool[NGRAPHS * 68];
__device__ int   d_is64;

// ---------------- small helpers ----------------
__device__ __forceinline__ float lrelu(float x) { return x > 0.f ? x : 0.2f * x; }
__device__ __forceinline__ float elu1(float x) { return x > 0.f ? x : __expf(x) - 1.f; }
__device__ __forceinline__ float seluf(float x) {
    const float a = 1.6732632423543772f, sc = 1.0507009873554805f;
    return x > 0.f ? sc * x : sc * a * expm1f(x);
}

// packed fp32x2 FMA (Blackwell; ptxas never emits this from C++)
__device__ __forceinline__ void ffma2(unsigned long long& d, unsigned long long a,
                                      unsigned long long b) {
    asm("fma.rn.f32x2 %0, %1, %2, %0;" : "+l"(d) : "l"(a), "l"(b));
}
__device__ __forceinline__ unsigned long long pack2(float x, float y) {
    unsigned long long r;
    asm("mov.b64 %0, {%1, %2};" : "=l"(r) : "f"(x), "f"(y));
    return r;
}
__device__ __forceinline__ float2 unpack2(unsigned long long v) {
    float2 f;
    asm("mov.b64 {%0, %1}, %2;" : "=f"(f.x), "=f"(f.y) : "l"(v));
    return f;
}

__device__ __forceinline__ int load_edge(const void* ei, long long pos) {
    if (d_is64) return (int)((const long long*)ei)[pos];
    return ((const int*)ei)[pos];
}

// ---------------- init: dtype detect + zero counters ----------------
__global__ void init_kernel(const int* ew) {
    int i = blockIdx.x * blockDim.x + threadIdx.x;
    if (i == 0) {
        int ok = 1;
        for (int j = 1; j < 256; j += 2)
            if (ew[j] != 0) ok = 0;
        d_is64 = ok;
    }
    if (i <= NNODES) d_off[i] = 0;
    if (i < NNODES) d_cursor[i] = 0;
}

__global__ void count_kernel(const void* ei) {
    int e = blockIdx.x * blockDim.x + threadIdx.x;
    if (e < NEDGES) {
        int d = load_edge(ei, (long long)NEDGES + e);
        atomicAdd(&d_off[d + 1], 1);
    }
}

// multi-block inclusive scan
__global__ void scan_blocks() {
    __shared__ int s[1024];
    int tid = threadIdx.x;
    int idx = blockIdx.x * 1024 + tid;
    int v = (idx <= NNODES) ? d_off[idx] : 0;
    s[tid] = v;
    __syncthreads();
    for (int off = 1; off < 1024; off <<= 1) {
        int t = (tid >= off) ? s[tid - off] : 0;
        __syncthreads();
        s[tid] += t;
        __syncthreads();
    }
    if (idx <= NNODES) d_off[idx] = s[tid];
    if (tid == 1023) d_bsum[blockIdx.x] = s[1023];
}

__global__ void scan_sums() {
    __shared__ int s[64];
    int tid = threadIdx.x;
    s[tid] = (tid < SCAN_NBLK) ? d_bsum[tid] : 0;
    __syncthreads();
    for (int off = 1; off < 64; off <<= 1) {
        int t = (tid >= off) ? s[tid - off] : 0;
        __syncthreads();
        s[tid] += t;
        __syncthreads();
    }
    d_bsum[tid] = s[tid];
}

__global__ void scan_add() {
    int b = blockIdx.x + 1;
    int idx = b * 1024 + threadIdx.x;
    if (idx <= NNODES) d_off[idx] += d_bsum[b - 1];
}

__global__ void scatter_kernel(const void* ei) {
    int e = blockIdx.x * blockDim.x + threadIdx.x;
    if (e < NEDGES) {
        int sN = load_edge(ei, e);
        int d = load_edge(ei, (long long)NEDGES + e);
        int p = atomicAdd(&d_cursor[d], 1);
        d_srcs[d_off[d] + p] = sN;
    }
}

// ---------------- GraphNorm: one block per graph ----------------
__global__ void graphnorm_kernel(const float* __restrict__ x, const float* __restrict__ w,
                                 const float* __restrict__ b, const float* __restrict__ ms) {
    int g = blockIdx.x;
    __shared__ float red[8][16];
    __shared__ float mv[16], vv[16];
    int t = threadIdx.x;           // 128 threads
    int f = t & 15, i0 = t >> 4;
    const float* xg = x + (size_t)g * NPG * FIN;
    float s = 0.f;
    for (int i = i0; i < NPG; i += 8) s += xg[i * FIN + f];
    red[i0][f] = s;
    __syncthreads();
    if (t < 16) {
        float m = 0.f;
        for (int j = 0; j < 8; j++) m += red[j][t];
        mv[t] = m * (1.f / NPG);
    }
    __syncthreads();
    float mm = mv[f] * ms[f];
    float sv = 0.f;
    for (int i = i0; i < NPG; i += 8) {
        float o = xg[i * FIN + f] - mm;
        sv += o * o;
    }
    __syncthreads();
    red[i0][f] = sv;
    __syncthreads();
    if (t < 16) {
        float v = 0.f;
        for (int j = 0; j < 8; j++) v += red[j][t];
        vv[t] = v * (1.f / NPG);
    }
    __syncthreads();
    float inv = rsqrtf(vv[f] + 1e-5f) * w[f];
    float bb = b[f];
    for (int i = i0; i < NPG; i += 8) {
        float o = xg[i * FIN + f] - mm;
        d_h0[(size_t)(g * NPG + i) * FIN + f] = o * inv + bb;
    }
}

// ---------------- SGEMM: 128x64 tile, 128 threads, 8x8/thread, FFMA2 ----------------
// __launch_bounds__(128,2): 256-reg budget so ptxas can keep a register-level
// pipeline of LDS fragments (load k+1 while FFMAing k) without spilling.
__global__ void __launch_bounds__(128, 2)
sgemm_att(const float* __restrict__ A, const float* __restrict__ B,
          float* __restrict__ C, int M, int K, int Nn,
          const float* __restrict__ atts, const float* __restrict__ attd, int H) {
    constexpr int BM = 128, BN = 64, BK = 16;
    __shared__ float As[2][BK][BM];   // 16 KB
    __shared__ float Bs[2][BK][BN];   // 8 KB
    const int tid = threadIdx.x;      // 128
    const int tx = tid & 7;           // 8 col groups (8 cols)
    const int ty = tid >> 3;          // 16 row groups (8 rows)
    const int row0 = blockIdx.x * BM;
    const int col0 = blockIdx.y * BN;
    const int hh = blockIdx.y;

    // staging indices (constant per thread)
    const int ak4 = (tid & 3) * 4;    // A k-offset within chunk
    const int am = tid >> 2;          // A base m (+32 per sub-iter)
    const int bn4 = (tid & 15) * 4;   // B col offset
    const int bk = tid >> 4;          // B base k (+8 per sub-iter)

    unsigned long long acc2[4][8];
#pragma unroll
    for (int i = 0; i < 4; i++)
#pragma unroll
        for (int j = 0; j < 8; j++) acc2[i][j] = 0ull;

    float4 ar[4], br[2];
    const int nIt = K / BK;

    // prologue: load chunk 0
#pragma unroll
    for (int it = 0; it < 4; it++) {
        int row = row0 + am + it * 32;
        ar[it] = (row < M) ? *(const float4*)(A + (size_t)row * K + ak4)
                           : make_float4(0.f, 0.f, 0.f, 0.f);
    }
#pragma unroll
    for (int it = 0; it < 2; it++)
        br[it] = *(const float4*)(B + (size_t)(bk + it * 8) * Nn + col0 + bn4);
#pragma unroll
    for (int it = 0; it < 4; it++) {
        int m = am + it * 32;
        As[0][ak4 + 0][m] = ar[it].x;
        As[0][ak4 + 1][m] = ar[it].y;
        As[0][ak4 + 2][m] = ar[it].z;
        As[0][ak4 + 3][m] = ar[it].w;
    }
#pragma unroll
    for (int it = 0; it < 2; it++)
        *(float4*)(&Bs[0][bk + it * 8][bn4]) = br[it];
    __syncthreads();

    for (int itK = 0; itK < nIt; itK++) {
        const int buf = itK & 1;
        const bool has_next = (itK + 1) < nIt;
        if (has_next) {
            const int k0 = (itK + 1) * BK;
#pragma unroll
            for (int it = 0; it < 4; it++) {
                int row = row0 + am + it * 32;
                ar[it] = (row < M) ? *(const float4*)(A + (size_t)row * K + k0 + ak4)
                                   : make_float4(0.f, 0.f, 0.f, 0.f);
            }
#pragma unroll
            for (int it = 0; it < 2; it++)
                br[it] = *(const float4*)(B + (size_t)(k0 + bk + it * 8) * Nn + col0 + bn4);
        }
        // register-level pipeline over k: load fragments for k+1 while FFMAing k
        ulonglong2 pA0[2], pA1[2];
        float4 pB0[2], pB1[2];
        pA0[0] = *(const ulonglong2*)(&As[buf][0][ty * 8]);
        pA1[0] = *(const ulonglong2*)(&As[buf][0][ty * 8 + 4]);
        pB0[0] = *(const float4*)(&Bs[buf][0][tx * 8]);
        pB1[0] = *(const float4*)(&Bs[buf][0][tx * 8 + 4]);
#pragma unroll
        for (int k = 0; k < BK; k++) {
            const int cur = k & 1, nxt = cur ^ 1;
            if (k + 1 < BK) {
                pA0[nxt] = *(const ulonglong2*)(&As[buf][k + 1][ty * 8]);
                pA1[nxt] = *(const ulonglong2*)(&As[buf][k + 1][ty * 8 + 4]);
                pB0[nxt] = *(const float4*)(&Bs[buf][k + 1][tx * 8]);
                pB1[nxt] = *(const float4*)(&Bs[buf][k + 1][tx * 8 + 4]);
            }
            unsigned long long av[4] = {pA0[cur].x, pA0[cur].y, pA1[cur].x, pA1[cur].y};
            unsigned long long bv[8];
            bv[0] = pack2(pB0[cur].x, pB0[cur].x);
            bv[1] = pack2(pB0[cur].y, pB0[cur].y);
            bv[2] = pack2(pB0[cur].z, pB0[cur].z);
            bv[3] = pack2(pB0[cur].w, pB0[cur].w);
            bv[4] = pack2(pB1[cur].x, pB1[cur].x);
            bv[5] = pack2(pB1[cur].y, pB1[cur].y);
            bv[6] = pack2(pB1[cur].z, pB1[cur].z);
            bv[7] = pack2(pB1[cur].w, pB1[cur].w);
#pragma unroll
            for (int i = 0; i < 4; i++)
#pragma unroll
                for (int j = 0; j < 8; j++) ffma2(acc2[i][j], av[i], bv[j]);
        }
        if (has_next) {
            const int nb = buf ^ 1;
#pragma unroll
            for (int it = 0; it < 4; it++) {
                int m = am + it * 32;
                As[nb][ak4 + 0][m] = ar[it].x;
                As[nb][ak4 + 1][m] = ar[it].y;
                As[nb][ak4 + 2][m] = ar[it].z;
                As[nb][ak4 + 3][m] = ar[it].w;
            }
#pragma unroll
            for (int it = 0; it < 2; it++)
                *(float4*)(&Bs[nb][bk + it * 8][bn4]) = br[it];
            __syncthreads();
        }
    }

    // epilogue: per row-pair, unpack, store C, compute att dots (no accf array)
    float atS[8], atD[8];
#pragma unroll
    for (int j = 0; j < 8; j++) {
        atS[j] = atts[hh * 64 + tx * 8 + j];
        atD[j] = attd[hh * 64 + tx * 8 + j];
    }
    float* redS = &As[0][0][0];           // 1024 floats
    float* redD = &As[0][0][0] + 1024;    // 1024 floats

    __syncthreads();
#pragma unroll
    for (int p = 0; p < 4; p++) {
        float v0[8], v1[8];
#pragma unroll
        for (int j = 0; j < 8; j++) {
            float2 u = unpack2(acc2[p][j]);
            v0[j] = u.x;
            v1[j] = u.y;
        }
        int r0 = row0 + ty * 8 + 2 * p;
        if (r0 < M) {
            float* cp = C + (size_t)r0 * Nn + col0 + tx * 8;
            *(float4*)cp = make_float4(v0[0], v0[1], v0[2], v0[3]);
            *(float4*)(cp + 4) = make_float4(v0[4], v0[5], v0[6], v0[7]);
        }
        int r1 = r0 + 1;
        if (r1 < M) {
            float* cp = C + (size_t)r1 * Nn + col0 + tx * 8;
            *(float4*)cp = make_float4(v1[0], v1[1], v1[2], v1[3]);
            *(float4*)(cp + 4) = make_float4(v1[4], v1[5], v1[6], v1[7]);
        }
        float s0 = 0.f, d0 = 0.f, s1 = 0.f, d1 = 0.f;
#pragma unroll
        for (int j = 0; j < 8; j++) {
            s0 += v0[j] * atS[j];
            d0 += v0[j] * atD[j];
            s1 += v1[j] * atS[j];
            d1 += v1[j] * atD[j];
        }
        redS[(ty * 8 + 2 * p) * 8 + tx] = s0;
        redD[(ty * 8 + 2 * p) * 8 + tx] = d0;
        redS[(ty * 8 + 2 * p + 1) * 8 + tx] = s1;
        redD[(ty * 8 + 2 * p + 1) * 8 + tx] = d1;
    }
    __syncthreads();
    {
        float s = 0.f, d = 0.f;
#pragma unroll
        for (int t = 0; t < 8; t++) {
            s += redS[tid * 8 + t];
            d += redD[tid * 8 + t];
        }
        int node = row0 + tid;
        if (node < M) {
            d_asrc[(size_t)node * H + hh] = s;
            d_adst[(size_t)node * H + hh] = d;
        }
    }
}

// ---------------- GAT aggregation: one block/graph, features+logits+edges in SMEM ----------------
template <int H, int HC, bool DOELU>
__global__ void __launch_bounds__(512)
gat_agg_smem(const float* __restrict__ h, const float* __restrict__ bias,
             float* __restrict__ out) {
    extern __shared__ float sm[];
    float* f_sh = sm;                               // NPG*HC
    float* as_sh = sm + NPG * HC;                   // NPG*H
    float* ad_sh = as_sh + NPG * H;                 // NPG*H
    int* off_sh = (int*)(ad_sh + NPG * H);          // NPG+1
    unsigned char* e_sh = (unsigned char*)(off_sh + NPG + 1);  // EMAX

    int g = blockIdx.x;
    int base = g * NPG;
    int tid = threadIdx.x;  // 512

    const float4* src4 = (const float4*)(h + (size_t)base * HC);
    float4* dst4 = (float4*)f_sh;
    for (int i = tid; i < NPG * HC / 4; i += 512) dst4[i] = src4[i];
    for (int i = tid; i < NPG * H; i += 512) {
        as_sh[i] = d_asrc[(size_t)base * H + i];
        ad_sh[i] = d_adst[(size_t)base * H + i];
    }
    for (int i = tid; i <= NPG; i += 512) off_sh[i] = d_off[base + i];
    __syncthreads();

    int beg_g = off_sh[0];
    int ne = off_sh[NPG] - beg_g;
    bool fits = (ne <= EMAX);
    if (fits)
        for (int i = tid; i < ne; i += 512)
            e_sh[i] = (unsigned char)(d_srcs[beg_g + i] - base);
    __syncthreads();

    int lane = tid & 31, w = tid >> 5;  // 16 warps
    constexpr int R = HC / 32;
    float bi[R];
#pragma unroll
    for (int k = 0; k < R; k++) bi[k] = bias[lane + 32 * k];

    for (int n = w; n < NPG; n += 16) {
        float ad[H], ssum[H];
#pragma unroll
        for (int hh = 0; hh < H; hh++) ad[hh] = ad_sh[n * H + hh];
#pragma unroll
        for (int hh = 0; hh < H; hh++)
            ssum[hh] = __expf(lrelu(as_sh[n * H + hh] + ad[hh]));  // self-loop
        float acc[R];
#pragma unroll
        for (int k = 0; k < R; k++) acc[k] = ssum[k / 2] * f_sh[n * HC + lane + 32 * k];

        int eb = off_sh[n] - beg_g, ee = off_sh[n + 1] - beg_g;
        if (fits) {
            int i = eb;
            for (; i + 1 < ee; i += 2) {
                int s0 = e_sh[i], s1 = e_sh[i + 1];
                float w0[H], w1[H];
#pragma unroll
                for (int hh = 0; hh < H; hh++) {
                    w0[hh] = __expf(lrelu(as_sh[s0 * H + hh] + ad[hh]));
                    w1[hh] = __expf(lrelu(as_sh[s1 * H + hh] + ad[hh]));
                }
#pragma unroll
                for (int hh = 0; hh < H; hh++) ssum[hh] += w0[hh] + w1[hh];
#pragma unroll
                for (int k = 0; k < R; k++)
                    acc[k] += w0[k / 2] * f_sh[s0 * HC + lane + 32 * k] +
                              w1[k / 2] * f_sh[s1 * HC + lane + 32 * k];
            }
            if (i < ee) {
                int s0 = e_sh[i];
                float w0[H];
#pragma unroll
                for (int hh = 0; hh < H; hh++) {
                    w0[hh] = __expf(lrelu(as_sh[s0 * H + hh] + ad[hh]));
                    ssum[hh] += w0[hh];
                }
#pragma unroll
                for (int k = 0; k < R; k++) acc[k] += w0[k / 2] * f_sh[s0 * HC + lane + 32 * k];
            }
        } else {  // fallback keeps correctness if a graph exceeds EMAX edges
            for (int i = eb; i < ee; i++) {
                int s0 = d_srcs[beg_g + i] - base;
                float w0[H];
#pragma unroll
                for (int hh = 0; hh < H; hh++) {
                    w0[hh] = __expf(lrelu(as_sh[s0 * H + hh] + ad[hh]));
                    ssum[hh] += w0[hh];
                }
#pragma unroll
                for (int k = 0; k < R; k++) acc[k] += w0[k / 2] * f_sh[s0 * HC + lane + 32 * k];
            }
        }
#pragma unroll
        for (int k = 0; k < R; k++) {
            float v = acc[k] / ssum[k / 2] + bi[k];
            if (DOELU) v = elu1(v);
            out[(size_t)(base + n) * HC + lane + 32 * k] = v;
        }
    }
}

// ---------------- global mean pool + concat graph_input ----------------
__global__ void pool_kernel(const float* __restrict__ h, const float* __restrict__ ginput) {
    int g = blockIdx.x, c = threadIdx.x;  // 64 threads
    const float* hp = h + (size_t)g * NPG * 64;
    float s = 0.f;
    for (int i = 0; i < NPG; i++) s += hp[i * 64 + c];
    d_pool[g * 68 + c] = s * (1.0f / NPG);
    if (c < 4) d_pool[g * 68 + 64 + c] = ginput[g * 4 + c];
}

// ---------------- fused head ----------------
__global__ void head_kernel(const float* __restrict__ bn_g, const float* __restrict__ bn_b,
                            const float* __restrict__ bn_m, const float* __restrict__ bn_v,
                            const float* __restrict__ Wd1, const float* __restrict__ bd1,
                            const float* __restrict__ Wd2, const float* __restrict__ bd2,
                            const float* __restrict__ Wo, const float* __restrict__ bo,
                            float* __restrict__ out) {
    __shared__ float sg[68], t1s[64], t2s[64];
    int g = blockIdx.x, t = threadIdx.x;  // 128 threads
    if (t < 68) {
        float v = d_pool[g * 68 + t];
        v = (v - bn_m[t]) * rsqrtf(bn_v[t] + 1e-5f) * bn_g[t] + bn_b[t];
        sg[t] = v;
    }
    __syncthreads();
    if (t < 64) {
        float a = bd1[t];
        for (int i = 0; i < 68; i++) a += sg[i] * Wd1[i * 64 + t];
        t1s[t] = seluf(a);
    }
    __syncthreads();
    if (t < 64) {
        float a = bd2[t];
        for (int i = 0; i < 64; i++) a += t1s[i] * Wd2[i * 64 + t];
        t2s[t] = seluf(a);
    }
    __syncthreads();
    if (t == 0) {
        float o0 = bo[0], o1 = bo[1];
        for (int i = 0; i < 64; i++) {
            o0 += t2s[i] * Wo[i * 2];
            o1 += t2s[i] * Wo[i * 2 + 1];
        }
        float mx = fmaxf(o0, o1);
        float e0 = expf(o0 - mx), e1 = expf(o1 - mx);
        float s = e0 + e1;
        out[g * 2] = e0 / s;
        out[g * 2 + 1] = e1 / s;
    }
}

// ---------------- launch ----------------
extern "C" void kernel_launch(void* const* d_in, const int* in_sizes, int n_in,
                              void* d_out, int out_size) {
    const float* x = (const float*)d_in[0];
    const void* ei = d_in[1];
    const float* ginput = (const float*)d_in[2];
    const float* gn_w = (const float*)d_in[4];
    const float* gn_b = (const float*)d_in[5];
    const float* gn_ms = (const float*)d_in[6];
    const float* W1 = (const float*)d_in[7];
    const float* as1 = (const float*)d_in[8];
    const float* ad1 = (const float*)d_in[9];
    const float* b1 = (const float*)d_in[10];
    const float* W2 = (const float*)d_in[11];
    const float* as2 = (const float*)d_in[12];
    const float* ad2 = (const float*)d_in[13];
    const float* b2 = (const float*)d_in[14];
    const float* W3 = (const float*)d_in[15];
    const float* as3 = (const float*)d_in[16];
    const float* ad3 = (const float*)d_in[17];
    const float* b3 = (const float*)d_in[18];
    const float* bn_g = (const float*)d_in[19];
    const float* bn_b = (const float*)d_in[20];
    const float* bn_m = (const float*)d_in[21];
    const float* bn_v = (const float*)d_in[22];
    const float* Wd1 = (const float*)d_in[23];
    const float* bd1 = (const float*)d_in[24];
    const float* Wd2 = (const float*)d_in[25];
    const float* bd2 = (const float*)d_in[26];
    const float* Wo = (const float*)d_in[27];
    const float* bo = (const float*)d_in[28];
    float* out = (float*)d_out;

    float *pH0, *pHA, *pHB;
    cudaGetSymbolAddress((void**)&pH0, d_h0);
    cudaGetSymbolAddress((void**)&pHA, d_hA);
    cudaGetSymbolAddress((void**)&pHB, d_hB);

    const int SM_BIG = (NPG * 256 + NPG * 4 * 2) * 4 + (NPG + 1) * 4 + EMAX;   // ~108 KB
    const int SM_SMALL = (NPG * 64 + NPG * 1 * 2) * 4 + (NPG + 1) * 4 + EMAX;  // ~29 KB
    cudaFuncSetAttribute(gat_agg_smem<4, 256, true>,
                         cudaFuncAttributeMaxDynamicSharedMemorySize, SM_BIG);
    cudaFuncSetAttribute(gat_agg_smem<1, 64, false>,
                         cudaFuncAttributeMaxDynamicSharedMemorySize, SM_SMALL);

    const int gridM = (NNODES + 127) / 128;  // 391

    // (1) graphnorm  (2) init  (3) count  (4) sgemm L1  <- profiler slot
    graphnorm_kernel<<<NGRAPHS, 128>>>(x, gn_w, gn_b, gn_ms);
    init_kernel<<<(NNODES + 256) / 256, 256>>>((const int*)ei);
    count_kernel<<<(NEDGES + 255) / 256, 256>>>(ei);
    sgemm_att<<<dim3(gridM, 4), 128>>>(pH0, W1, pHA, NNODES, 16, 256, as1, ad1, 4);
    scan_blocks<<<SCAN_NBLK, 1024>>>();
    scan_sums<<<1, 64>>>();
    scan_add<<<SCAN_NBLK - 1, 1024>>>();
    scatter_kernel<<<(NEDGES + 255) / 256, 256>>>(ei);

    gat_agg_smem<4, 256, true><<<NGRAPHS, 512, SM_BIG>>>(pHA, b1, pHB);

    sgemm_att<<<dim3(gridM, 4), 128>>>(pHB, W2, pHA, NNODES, 256, 256, as2, ad2, 4);
    gat_agg_smem<4, 256, true><<<NGRAPHS, 512, SM_BIG>>>(pHA, b2, pHB);

    sgemm_att<<<dim3(gridM, 1), 128>>>(pHB, W3, pHA, NNODES, 256, 64, as3, ad3, 1);
    gat_agg_smem<1, 64, false><<<NGRAPHS, 512, SM_SMALL>>>(pHA, b3, pHB);

    pool_kernel<<<NGRAPHS, 64>>>(pHB, ginput);
    head_kernel<<<NGRAPHS, 128>>>(bn_g, bn_b, bn_m, bn_v, Wd1, bd1, Wd2, bd2, Wo, bo, out);
}

// round 15
// speedup vs baseline: 1.3685x; 1.3685x over previous
#include <cuda_runtime.h>
#include <cuda_bf16.h>
#include <cstdint>

#define NNODES 50000
#define NEDGES 500000
#define NGRAPHS 500
#define NPG 100
#define FIN 16
#define SCAN_NBLK ((NNODES + 1 + 1023) / 1024)   // 49
#define EMAX 2048

// ---------------- scratch (device globals; no allocation allowed) ----------------
__device__ float d_h0[NNODES * FIN];
__device__ float d_hA[NNODES * 256];
__device__ float d_hB[NNODES * 256];
__device__ float d_asrc[NNODES * 4];
__device__ float d_adst[NNODES * 4];
__device__ int   d_off[NNODES + 1];
__device__ int   d_cursor[NNODES];
__device__ int   d_srcs[NEDGES];
__device__ int   d_bsum[64];
__device__ float d_pool[NGRAPHS * 68];
__device__ int   d_is64;
// bf16 split buffers for tensor-core GEMM
__device__ __nv_bfloat16 d_Ahi[NNODES * 256];
__device__ __nv_bfloat16 d_Alo[NNODES * 256];
__device__ __nv_bfloat16 d_W2hi[256 * 256];
__device__ __nv_bfloat16 d_W2lo[256 * 256];
__device__ __nv_bfloat16 d_W3hi[64 * 256];
__device__ __nv_bfloat16 d_W3lo[64 * 256];

// ---------------- helpers ----------------
__device__ __forceinline__ float lrelu(float x) { return x > 0.f ? x : 0.2f * x; }
__device__ __forceinline__ float elu1(float x) { return x > 0.f ? x : __expf(x) - 1.f; }
__device__ __forceinline__ float seluf(float x) {
    const float a = 1.6732632423543772f, sc = 1.0507009873554805f;
    return x > 0.f ? sc * x : sc * a * expm1f(x);
}
__device__ __forceinline__ void ffma2(unsigned long long& d, unsigned long long a,
                                      unsigned long long b) {
    asm("fma.rn.f32x2 %0, %1, %2, %0;" : "+l"(d) : "l"(a), "l"(b));
}
__device__ __forceinline__ unsigned long long pack2(float x, float y) {
    unsigned long long r;
    asm("mov.b64 %0, {%1, %2};" : "=l"(r) : "f"(x), "f"(y));
    return r;
}
__device__ __forceinline__ float2 unpack2(unsigned long long v) {
    float2 f;
    asm("mov.b64 {%0, %1}, %2;" : "=f"(f.x), "=f"(f.y) : "l"(v));
    return f;
}
__device__ __forceinline__ int load_edge(const void* ei, long long pos) {
    if (d_is64) return (int)((const long long*)ei)[pos];
    return ((const int*)ei)[pos];
}

// legacy tensor-core mma (sm_80+; legal on compute_103 — no 'a' feature needed)
__device__ __forceinline__ void mma16816(float* d, const uint32_t* a, const uint32_t* b) {
    asm volatile(
        "mma.sync.aligned.m16n8k16.row.col.f32.bf16.bf16.f32 "
        "{%0,%1,%2,%3}, {%4,%5,%6,%7}, {%8,%9}, {%0,%1,%2,%3};"
        : "+f"(d[0]), "+f"(d[1]), "+f"(d[2]), "+f"(d[3])
        : "r"(a[0]), "r"(a[1]), "r"(a[2]), "r"(a[3]), "r"(b[0]), "r"(b[1]));
}

// ---------------- init: dtype detect + zero counters ----------------
__global__ void init_kernel(const int* ew) {
    int i = blockIdx.x * blockDim.x + threadIdx.x;
    if (i == 0) {
        int ok = 1;
        for (int j = 1; j < 256; j += 2)
            if (ew[j] != 0) ok = 0;
        d_is64 = ok;
    }
    if (i <= NNODES) d_off[i] = 0;
    if (i < NNODES) d_cursor[i] = 0;
}

__global__ void count_kernel(const void* ei) {
    int e = blockIdx.x * blockDim.x + threadIdx.x;
    if (e < NEDGES) {
        int d = load_edge(ei, (long long)NEDGES + e);
        atomicAdd(&d_off[d + 1], 1);
    }
}

__global__ void scan_blocks() {
    __shared__ int s[1024];
    int tid = threadIdx.x;
    int idx = blockIdx.x * 1024 + tid;
    int v = (idx <= NNODES) ? d_off[idx] : 0;
    s[tid] = v;
    __syncthreads();
    for (int off = 1; off < 1024; off <<= 1) {
        int t = (tid >= off) ? s[tid - off] : 0;
        __syncthreads();
        s[tid] += t;
        __syncthreads();
    }
    if (idx <= NNODES) d_off[idx] = s[tid];
    if (tid == 1023) d_bsum[blockIdx.x] = s[1023];
}

__global__ void scan_sums() {
    __shared__ int s[64];
    int tid = threadIdx.x;
    s[tid] = (tid < SCAN_NBLK) ? d_bsum[tid] : 0;
    __syncthreads();
    for (int off = 1; off < 64; off <<= 1) {
        int t = (tid >= off) ? s[tid - off] : 0;
        __syncthreads();
        s[tid] += t;
        __syncthreads();
    }
    d_bsum[tid] = s[tid];
}

__global__ void scan_add() {
    int b = blockIdx.x + 1;
    int idx = b * 1024 + threadIdx.x;
    if (idx <= NNODES) d_off[idx] += d_bsum[b - 1];
}

__global__ void scatter_kernel(const void* ei) {
    int e = blockIdx.x * blockDim.x + threadIdx.x;
    if (e < NEDGES) {
        int sN = load_edge(ei, e);
        int d = load_edge(ei, (long long)NEDGES + e);
        int p = atomicAdd(&d_cursor[d], 1);
        d_srcs[d_off[d] + p] = sN;
    }
}

// ---------------- GraphNorm ----------------
__global__ void graphnorm_kernel(const float* __restrict__ x, const float* __restrict__ w,
                                 const float* __restrict__ b, const float* __restrict__ ms) {
    int g = blockIdx.x;
    __shared__ float red[8][16];
    __shared__ float mv[16], vv[16];
    int t = threadIdx.x;
    int f = t & 15, i0 = t >> 4;
    const float* xg = x + (size_t)g * NPG * FIN;
    float s = 0.f;
    for (int i = i0; i < NPG; i += 8) s += xg[i * FIN + f];
    red[i0][f] = s;
    __syncthreads();
    if (t < 16) {
        float m = 0.f;
        for (int j = 0; j < 8; j++) m += red[j][t];
        mv[t] = m * (1.f / NPG);
    }
    __syncthreads();
    float mm = mv[f] * ms[f];
    float sv = 0.f;
    for (int i = i0; i < NPG; i += 8) {
        float o = xg[i * FIN + f] - mm;
        sv += o * o;
    }
    __syncthreads();
    red[i0][f] = sv;
    __syncthreads();
    if (t < 16) {
        float v = 0.f;
        for (int j = 0; j < 8; j++) v += red[j][t];
        vv[t] = v * (1.f / NPG);
    }
    __syncthreads();
    float inv = rsqrtf(vv[f] + 1e-5f) * w[f];
    float bb = b[f];
    for (int i = i0; i < NPG; i += 8) {
        float o = xg[i * FIN + f] - mm;
        d_h0[(size_t)(g * NPG + i) * FIN + f] = o * inv + bb;
    }
}

// ---------------- scalar SGEMM (R6, for layer 1 K=16) ----------------
__global__ void __launch_bounds__(128, 3)
sgemm_att(const float* __restrict__ A, const float* __restrict__ B,
          float* __restrict__ C, int M, int K, int Nn,
          const float* __restrict__ atts, const float* __restrict__ attd, int H) {
    constexpr int BM = 128, BN = 64, BK = 16;
    __shared__ float As[BK][BM];
    __shared__ float Bs[BK][BN];
    const int tid = threadIdx.x;
    const int tx = tid & 7;
    const int ty = tid >> 3;
    const int row0 = blockIdx.x * BM;
    const int col0 = blockIdx.y * BN;
    const int hh = blockIdx.y;

    unsigned long long acc2[4][8];
#pragma unroll
    for (int i = 0; i < 4; i++)
#pragma unroll
        for (int j = 0; j < 8; j++) acc2[i][j] = 0ull;

    for (int k0 = 0; k0 < K; k0 += BK) {
#pragma unroll
        for (int it = 0; it < 4; it++) {
            int idx = tid + it * 128;
            int m = idx >> 2;
            int k4 = idx & 3;
            float4 v = make_float4(0.f, 0.f, 0.f, 0.f);
            int row = row0 + m;
            if (row < M) v = *(const float4*)(A + (size_t)row * K + k0 + k4 * 4);
            As[k4 * 4 + 0][m] = v.x;
            As[k4 * 4 + 1][m] = v.y;
            As[k4 * 4 + 2][m] = v.z;
            As[k4 * 4 + 3][m] = v.w;
        }
#pragma unroll
        for (int it = 0; it < 2; it++) {
            int idx = tid + it * 128;
            int k = idx >> 4;
            int n4 = idx & 15;
            *(float4*)(&Bs[k][n4 * 4]) =
                *(const float4*)(B + (size_t)(k0 + k) * Nn + col0 + n4 * 4);
        }
        __syncthreads();
#pragma unroll
        for (int k = 0; k < BK; k++) {
            ulonglong2 a01 = *(const ulonglong2*)(&As[k][ty * 8]);
            ulonglong2 a23 = *(const ulonglong2*)(&As[k][ty * 8 + 4]);
            float4 bva = *(const float4*)(&Bs[k][tx * 8]);
            float4 bvb = *(const float4*)(&Bs[k][tx * 8 + 4]);
            unsigned long long av[4] = {a01.x, a01.y, a23.x, a23.y};
            unsigned long long bv[8];
            bv[0] = pack2(bva.x, bva.x);
            bv[1] = pack2(bva.y, bva.y);
            bv[2] = pack2(bva.z, bva.z);
            bv[3] = pack2(bva.w, bva.w);
            bv[4] = pack2(bvb.x, bvb.x);
            bv[5] = pack2(bvb.y, bvb.y);
            bv[6] = pack2(bvb.z, bvb.z);
            bv[7] = pack2(bvb.w, bvb.w);
#pragma unroll
            for (int i = 0; i < 4; i++)
#pragma unroll
                for (int j = 0; j < 8; j++) ffma2(acc2[i][j], av[i], bv[j]);
        }
        __syncthreads();
    }

    float atS[8], atD[8];
#pragma unroll
    for (int j = 0; j < 8; j++) {
        atS[j] = atts[hh * 64 + tx * 8 + j];
        atD[j] = attd[hh * 64 + tx * 8 + j];
    }
    float* redS = &As[0][0];
    float* redD = &As[0][0] + 1024;

    __syncthreads();
#pragma unroll
    for (int p = 0; p < 4; p++) {
        float v0[8], v1[8];
#pragma unroll
        for (int j = 0; j < 8; j++) {
            float2 u = unpack2(acc2[p][j]);
            v0[j] = u.x;
            v1[j] = u.y;
        }
        int r0 = row0 + ty * 8 + 2 * p;
        if (r0 < M) {
            float* cp = C + (size_t)r0 * Nn + col0 + tx * 8;
            *(float4*)cp = make_float4(v0[0], v0[1], v0[2], v0[3]);
            *(float4*)(cp + 4) = make_float4(v0[4], v0[5], v0[6], v0[7]);
        }
        int r1 = r0 + 1;
        if (r1 < M) {
            float* cp = C + (size_t)r1 * Nn + col0 + tx * 8;
            *(float4*)cp = make_float4(v1[0], v1[1], v1[2], v1[3]);
            *(float4*)(cp + 4) = make_float4(v1[4], v1[5], v1[6], v1[7]);
        }
        float s0 = 0.f, d0 = 0.f, s1 = 0.f, d1 = 0.f;
#pragma unroll
        for (int j = 0; j < 8; j++) {
            s0 += v0[j] * atS[j];
            d0 += v0[j] * atD[j];
            s1 += v1[j] * atS[j];
            d1 += v1[j] * atD[j];
        }
        redS[(ty * 8 + 2 * p) * 8 + tx] = s0;
        redD[(ty * 8 + 2 * p) * 8 + tx] = d0;
        redS[(ty * 8 + 2 * p + 1) * 8 + tx] = s1;
        redD[(ty * 8 + 2 * p + 1) * 8 + tx] = d1;
    }
    __syncthreads();
    {
        float s = 0.f, d = 0.f;
#pragma unroll
        for (int t = 0; t < 8; t++) {
            s += redS[tid * 8 + t];
            d += redD[tid * 8 + t];
        }
        int node = row0 + tid;
        if (node < M) {
            d_asrc[(size_t)node * H + hh] = s;
            d_adst[(size_t)node * H + hh] = d;
        }
    }
}

// ---------------- bf16 split conversions ----------------
__global__ void convA_kernel(const float* __restrict__ x, int n2) {
    int i = blockIdx.x * blockDim.x + threadIdx.x;
    if (i < n2) {
        float2 v = ((const float2*)x)[i];
        __nv_bfloat16 h0 = __float2bfloat16(v.x), h1 = __float2bfloat16(v.y);
        __nv_bfloat16 l0 = __float2bfloat16(v.x - __bfloat162float(h0));
        __nv_bfloat16 l1 = __float2bfloat16(v.y - __bfloat162float(h1));
        ((__nv_bfloat162*)d_Ahi)[i] = __halves2bfloat162(h0, h1);
        ((__nv_bfloat162*)d_Alo)[i] = __halves2bfloat162(l0, l1);
    }
}
// W [K,N] fp32 -> W^T [N,K] bf16 hi/lo
__global__ void convW_kernel(const float* __restrict__ W, __nv_bfloat16* __restrict__ hi,
                             __nv_bfloat16* __restrict__ lo, int K, int N) {
    int i = blockIdx.x * blockDim.x + threadIdx.x;
    if (i < K * N) {
        int n = i / K, k = i - n * K;
        float v = W[(size_t)k * N + n];
        __nv_bfloat16 h = __float2bfloat16(v);
        hi[i] = h;
        lo[i] = __float2bfloat16(v - __bfloat162float(h));
    }
}

// ---------------- tensor-core GEMM via mma.sync (bf16 hi/lo split, fused att epilogue) ----------
// A: [M,K] bf16 row-major (hi/lo). B: [Nn,K] bf16 (W^T, hi/lo).
// Block tile 128x64, 4 warps (warp tile 64x32 = 4x4 m16n8k16 atoms).
// SMEM rows padded to 72 bf16 (144 B) -> fragment LDS are conflict-free (bank == lane).
#define ASTR 72
__global__ void __launch_bounds__(128, 2)
mma_gemm_att(const __nv_bfloat16* __restrict__ Ahi, const __nv_bfloat16* __restrict__ Alo,
             const __nv_bfloat16* __restrict__ Bhi, const __nv_bfloat16* __restrict__ Blo,
             float* __restrict__ C, int M, int K, int Nn,
             const float* __restrict__ atts, const float* __restrict__ attd, int H) {
    extern __shared__ __nv_bfloat16 sm[];
    __nv_bfloat16* sAH = sm;                    // 128*72
    __nv_bfloat16* sAL = sm + 128 * ASTR;       // 128*72
    __nv_bfloat16* sBH = sm + 256 * ASTR;       // 64*72
    __nv_bfloat16* sBL = sm + 256 * ASTR + 64 * ASTR;

    const int tid = threadIdx.x;
    const int wid = tid >> 5, lane = tid & 31;
    const int g = lane >> 2, tig = lane & 3;
    const int wm = wid & 1, wn = wid >> 1;      // warp covers rows [wm*64,+64), cols [wn*32,+32)
    const int row0 = blockIdx.x * 128, col0 = blockIdx.y * 64, hh = blockIdx.y;

    float acc[4][4][4];
#pragma unroll
    for (int m = 0; m < 4; m++)
#pragma unroll
        for (int n = 0; n < 4; n++)
#pragma unroll
            for (int r = 0; r < 4; r++) acc[m][n][r] = 0.f;

    const int nCh = K >> 6;
    for (int c = 0; c < nCh; c++) {
        // stage A: 128 rows x 64 bf16 (8 uint4/row) per operand
#pragma unroll
        for (int it = 0; it < 8; it++) {
            int idx = tid + it * 128;
            int r = idx >> 3, j = idx & 7;
            int grow = row0 + r;
            uint4 vh = make_uint4(0, 0, 0, 0), vl = make_uint4(0, 0, 0, 0);
            if (grow < M) {
                size_t off = (size_t)grow * K + c * 64 + j * 8;
                vh = *(const uint4*)(Ahi + off);
                vl = *(const uint4*)(Alo + off);
            }
            *(uint4*)(sAH + r * ASTR + j * 8) = vh;
            *(uint4*)(sAL + r * ASTR + j * 8) = vl;
        }
        // stage B: 64 rows x 64 bf16 per operand
#pragma unroll
        for (int it = 0; it < 4; it++) {
            int idx = tid + it * 128;
            int n = idx >> 3, j = idx & 7;
            size_t off = (size_t)(col0 + n) * K + c * 64 + j * 8;
            *(uint4*)(sBH + n * ASTR + j * 8) = *(const uint4*)(Bhi + off);
            *(uint4*)(sBL + n * ASTR + j * 8) = *(const uint4*)(Blo + off);
        }
        __syncthreads();
#pragma unroll
        for (int ks = 0; ks < 4; ks++) {
            const int kb = ks * 16 + tig * 2;
            uint32_t ah[4][4], al[4][4], bf[4][2];
#pragma unroll
            for (int m = 0; m < 4; m++) {
                int r = wm * 64 + m * 16 + g;
                ah[m][0] = *(const uint32_t*)(sAH + r * ASTR + kb);
                ah[m][1] = *(const uint32_t*)(sAH + (r + 8) * ASTR + kb);
                ah[m][2] = *(const uint32_t*)(sAH + r * ASTR + kb + 8);
                ah[m][3] = *(const uint32_t*)(sAH + (r + 8) * ASTR + kb + 8);
                al[m][0] = *(const uint32_t*)(sAL + r * ASTR + kb);
                al[m][1] = *(const uint32_t*)(sAL + (r + 8) * ASTR + kb);
                al[m][2] = *(const uint32_t*)(sAL + r * ASTR + kb + 8);
                al[m][3] = *(const uint32_t*)(sAL + (r + 8) * ASTR + kb + 8);
            }
#pragma unroll
            for (int n = 0; n < 4; n++) {
                int bn = wn * 32 + n * 8 + g;
                bf[n][0] = *(const uint32_t*)(sBH + bn * ASTR + kb);
                bf[n][1] = *(const uint32_t*)(sBH + bn * ASTR + kb + 8);
            }
#pragma unroll
            for (int m = 0; m < 4; m++)
#pragma unroll
                for (int n = 0; n < 4; n++) {
                    mma16816(acc[m][n], ah[m], bf[n]);   // hi*hi
                    mma16816(acc[m][n], al[m], bf[n]);   // lo*hi
                }
#pragma unroll
            for (int n = 0; n < 4; n++) {
                int bn = wn * 32 + n * 8 + g;
                bf[n][0] = *(const uint32_t*)(sBL + bn * ASTR + kb);
                bf[n][1] = *(const uint32_t*)(sBL + bn * ASTR + kb + 8);
            }
#pragma unroll
            for (int m = 0; m < 4; m++)
#pragma unroll
                for (int n = 0; n < 4; n++)
                    mma16816(acc[m][n], ah[m], bf[n]);   // hi*lo
        }
        __syncthreads();
    }

    // epilogue: store C + fused att dots
    const float* aS = atts + hh * 64;
    const float* aD = attd + hh * 64;
    float sv[4][2], dv[4][2];
#pragma unroll
    for (int m = 0; m < 4; m++) {
        sv[m][0] = sv[m][1] = dv[m][0] = dv[m][1] = 0.f;
    }
#pragma unroll
    for (int m = 0; m < 4; m++) {
        int row = row0 + wm * 64 + m * 16 + g;
#pragma unroll
        for (int n = 0; n < 4; n++) {
            int col = wn * 32 + n * 8 + tig * 2;
            float w0 = aS[col], w1 = aS[col + 1];
            float u0 = aD[col], u1 = aD[col + 1];
            sv[m][0] += acc[m][n][0] * w0 + acc[m][n][1] * w1;
            sv[m][1] += acc[m][n][2] * w0 + acc[m][n][3] * w1;
            dv[m][0] += acc[m][n][0] * u0 + acc[m][n][1] * u1;
            dv[m][1] += acc[m][n][2] * u0 + acc[m][n][3] * u1;
            if (row < M)
                *(float2*)(C + (size_t)row * Nn + col0 + col) =
                    make_float2(acc[m][n][0], acc[m][n][1]);
            if (row + 8 < M)
                *(float2*)(C + (size_t)(row + 8) * Nn + col0 + col) =
                    make_float2(acc[m][n][2], acc[m][n][3]);
        }
    }
    // quad reduce (lanes within a quad share rows, differ in tig)
#pragma unroll
    for (int m = 0; m < 4; m++)
#pragma unroll
        for (int hlf = 0; hlf < 2; hlf++) {
            float s = sv[m][hlf], d = dv[m][hlf];
            s += __shfl_xor_sync(0xffffffffu, s, 1);
            s += __shfl_xor_sync(0xffffffffu, s, 2);
            d += __shfl_xor_sync(0xffffffffu, d, 1);
            d += __shfl_xor_sync(0xffffffffu, d, 2);
            sv[m][hlf] = s;
            dv[m][hlf] = d;
        }
    float* redS = (float*)sm;          // [2][128]
    float* redD = (float*)sm + 256;
    __syncthreads();
    if (tig == 0) {
#pragma unroll
        for (int m = 0; m < 4; m++)
#pragma unroll
            for (int hlf = 0; hlf < 2; hlf++) {
                int lr = wm * 64 + m * 16 + g + hlf * 8;
                redS[wn * 128 + lr] = sv[m][hlf];
                redD[wn * 128 + lr] = dv[m][hlf];
            }
    }
    __syncthreads();
    {
        int node = row0 + tid;
        if (node < M) {
            d_asrc[(size_t)node * H + hh] = redS[tid] + redS[128 + tid];
            d_adst[(size_t)node * H + hh] = redD[tid] + redD[128 + tid];
        }
    }
}

// ---------------- GAT aggregation (unchanged) ----------------
template <int H, int HC, bool DOELU>
__global__ void __launch_bounds__(512)
gat_agg_smem(const float* __restrict__ h, const float* __restrict__ bias,
             float* __restrict__ out) {
    extern __shared__ float smf[];
    float* f_sh = smf;
    float* as_sh = smf + NPG * HC;
    float* ad_sh = as_sh + NPG * H;
    int* off_sh = (int*)(ad_sh + NPG * H);
    unsigned char* e_sh = (unsigned char*)(off_sh + NPG + 1);

    int g = blockIdx.x;
    int base = g * NPG;
    int tid = threadIdx.x;

    const float4* src4 = (const float4*)(h + (size_t)base * HC);
    float4* dst4 = (float4*)f_sh;
    for (int i = tid; i < NPG * HC / 4; i += 512) dst4[i] = src4[i];
    for (int i = tid; i < NPG * H; i += 512) {
        as_sh[i] = d_asrc[(size_t)base * H + i];
        ad_sh[i] = d_adst[(size_t)base * H + i];
    }
    for (int i = tid; i <= NPG; i += 512) off_sh[i] = d_off[base + i];
    __syncthreads();

    int beg_g = off_sh[0];
    int ne = off_sh[NPG] - beg_g;
    bool fits = (ne <= EMAX);
    if (fits)
        for (int i = tid; i < ne; i += 512)
            e_sh[i] = (unsigned char)(d_srcs[beg_g + i] - base);
    __syncthreads();

    int lane = tid & 31, w = tid >> 5;
    constexpr int R = HC / 32;
    float bi[R];
#pragma unroll
    for (int k = 0; k < R; k++) bi[k] = bias[lane + 32 * k];

    for (int n = w; n < NPG; n += 16) {
        float ad[H], ssum[H];
#pragma unroll
        for (int hh = 0; hh < H; hh++) ad[hh] = ad_sh[n * H + hh];
#pragma unroll
        for (int hh = 0; hh < H; hh++)
            ssum[hh] = __expf(lrelu(as_sh[n * H + hh] + ad[hh]));
        float acc[R];
#pragma unroll
        for (int k = 0; k < R; k++) acc[k] = ssum[k / 2] * f_sh[n * HC + lane + 32 * k];

        int eb = off_sh[n] - beg_g, ee = off_sh[n + 1] - beg_g;
        if (fits) {
            int i = eb;
            for (; i + 1 < ee; i += 2) {
                int s0 = e_sh[i], s1 = e_sh[i + 1];
                float w0[H], w1[H];
#pragma unroll
                for (int hh = 0; hh < H; hh++) {
                    w0[hh] = __expf(lrelu(as_sh[s0 * H + hh] + ad[hh]));
                    w1[hh] = __expf(lrelu(as_sh[s1 * H + hh] + ad[hh]));
                }
#pragma unroll
                for (int hh = 0; hh < H; hh++) ssum[hh] += w0[hh] + w1[hh];
#pragma unroll
                for (int k = 0; k < R; k++)
                    acc[k] += w0[k / 2] * f_sh[s0 * HC + lane + 32 * k] +
                              w1[k / 2] * f_sh[s1 * HC + lane + 32 * k];
            }
            if (i < ee) {
                int s0 = e_sh[i];
                float w0[H];
#pragma unroll
                for (int hh = 0; hh < H; hh++) {
                    w0[hh] = __expf(lrelu(as_sh[s0 * H + hh] + ad[hh]));
                    ssum[hh] += w0[hh];
                }
#pragma unroll
                for (int k = 0; k < R; k++) acc[k] += w0[k / 2] * f_sh[s0 * HC + lane + 32 * k];
            }
        } else {
            for (int i = eb; i < ee; i++) {
                int s0 = d_srcs[beg_g + i] - base;
                float w0[H];
#pragma unroll
                for (int hh = 0; hh < H; hh++) {
                    w0[hh] = __expf(lrelu(as_sh[s0 * H + hh] + ad[hh]));
                    ssum[hh] += w0[hh];
                }
#pragma unroll
                for (int k = 0; k < R; k++) acc[k] += w0[k / 2] * f_sh[s0 * HC + lane + 32 * k];
            }
        }
#pragma unroll
        for (int k = 0; k < R; k++) {
            float v = acc[k] / ssum[k / 2] + bi[k];
            if (DOELU) v = elu1(v);
            out[(size_t)(base + n) * HC + lane + 32 * k] = v;
        }
    }
}

// ---------------- pool + head (unchanged) ----------------
__global__ void pool_kernel(const float* __restrict__ h, const float* __restrict__ ginput) {
    int g = blockIdx.x, c = threadIdx.x;
    const float* hp = h + (size_t)g * NPG * 64;
    float s = 0.f;
    for (int i = 0; i < NPG; i++) s += hp[i * 64 + c];
    d_pool[g * 68 + c] = s * (1.0f / NPG);
    if (c < 4) d_pool[g * 68 + 64 + c] = ginput[g * 4 + c];
}

__global__ void head_kernel(const float* __restrict__ bn_g, const float* __restrict__ bn_b,
                            const float* __restrict__ bn_m, const float* __restrict__ bn_v,
                            const float* __restrict__ Wd1, const float* __restrict__ bd1,
                            const float* __restrict__ Wd2, const float* __restrict__ bd2,
                            const float* __restrict__ Wo, const float* __restrict__ bo,
                            float* __restrict__ out) {
    __shared__ float sg[68], t1s[64], t2s[64];
    int g = blockIdx.x, t = threadIdx.x;
    if (t < 68) {
        float v = d_pool[g * 68 + t];
        v = (v - bn_m[t]) * rsqrtf(bn_v[t] + 1e-5f) * bn_g[t] + bn_b[t];
        sg[t] = v;
    }
    __syncthreads();
    if (t < 64) {
        float a = bd1[t];
        for (int i = 0; i < 68; i++) a += sg[i] * Wd1[i * 64 + t];
        t1s[t] = seluf(a);
    }
    __syncthreads();
    if (t < 64) {
        float a = bd2[t];
        for (int i = 0; i < 64; i++) a += t1s[i] * Wd2[i * 64 + t];
        t2s[t] = seluf(a);
    }
    __syncthreads();
    if (t == 0) {
        float o0 = bo[0], o1 = bo[1];
        for (int i = 0; i < 64; i++) {
            o0 += t2s[i] * Wo[i * 2];
            o1 += t2s[i] * Wo[i * 2 + 1];
        }
        float mx = fmaxf(o0, o1);
        float e0 = expf(o0 - mx), e1 = expf(o1 - mx);
        float s = e0 + e1;
        out[g * 2] = e0 / s;
        out[g * 2 + 1] = e1 / s;
    }
}

// ---------------- launch ----------------
extern "C" void kernel_launch(void* const* d_in, const int* in_sizes, int n_in,
                              void* d_out, int out_size) {
    const float* x = (const float*)d_in[0];
    const void* ei = d_in[1];
    const float* ginput = (const float*)d_in[2];
    const float* gn_w = (const float*)d_in[4];
    const float* gn_b = (const float*)d_in[5];
    const float* gn_ms = (const float*)d_in[6];
    const float* W1 = (const float*)d_in[7];
    const float* as1 = (const float*)d_in[8];
    const float* ad1 = (const float*)d_in[9];
    const float* b1 = (const float*)d_in[10];
    const float* W2 = (const float*)d_in[11];
    const float* as2 = (const float*)d_in[12];
    const float* ad2 = (const float*)d_in[13];
    const float* b2 = (const float*)d_in[14];
    const float* W3 = (const float*)d_in[15];
    const float* as3 = (const float*)d_in[16];
    const float* ad3 = (const float*)d_in[17];
    const float* b3 = (const float*)d_in[18];
    const float* bn_g = (const float*)d_in[19];
    const float* bn_b = (const float*)d_in[20];
    const float* bn_m = (const float*)d_in[21];
    const float* bn_v = (const float*)d_in[22];
    const float* Wd1 = (const float*)d_in[23];
    const float* bd1 = (const float*)d_in[24];
    const float* Wd2 = (const float*)d_in[25];
    const float* bd2 = (const float*)d_in[26];
    const float* Wo = (const float*)d_in[27];
    const float* bo = (const float*)d_in[28];
    float* out = (float*)d_out;

    float *pH0, *pHA, *pHB;
    cudaGetSymbolAddress((void**)&pH0, d_h0);
    cudaGetSymbolAddress((void**)&pHA, d_hA);
    cudaGetSymbolAddress((void**)&pHB, d_hB);
    __nv_bfloat16 *pAhi, *pAlo, *pW2hi, *pW2lo, *pW3hi, *pW3lo;
    cudaGetSymbolAddress((void**)&pAhi, d_Ahi);
    cudaGetSymbolAddress((void**)&pAlo, d_Alo);
    cudaGetSymbolAddress((void**)&pW2hi, d_W2hi);
    cudaGetSymbolAddress((void**)&pW2lo, d_W2lo);
    cudaGetSymbolAddress((void**)&pW3hi, d_W3hi);
    cudaGetSymbolAddress((void**)&pW3lo, d_W3lo);

    const int SM_BIG = (NPG * 256 + NPG * 4 * 2) * 4 + (NPG + 1) * 4 + EMAX;
    const int SM_SMALL = (NPG * 64 + NPG * 1 * 2) * 4 + (NPG + 1) * 4 + EMAX;
    const int SM_MMA = (256 * ASTR + 128 * ASTR) * 2;  // 55296 B
    cudaFuncSetAttribute(gat_agg_smem<4, 256, true>,
                         cudaFuncAttributeMaxDynamicSharedMemorySize, SM_BIG);
    cudaFuncSetAttribute(gat_agg_smem<1, 64, false>,
                         cudaFuncAttributeMaxDynamicSharedMemorySize, SM_SMALL);
    cudaFuncSetAttribute(mma_gemm_att, cudaFuncAttributeMaxDynamicSharedMemorySize, SM_MMA);

    const int gridM = (NNODES + 127) / 128;  // 391
    const int nA2 = NNODES * 256 / 2;

    graphnorm_kernel<<<NGRAPHS, 128>>>(x, gn_w, gn_b, gn_ms);
    init_kernel<<<(NNODES + 256) / 256, 256>>>((const int*)ei);
    count_kernel<<<(NEDGES + 255) / 256, 256>>>(ei);
    sgemm_att<<<dim3(gridM, 4), 128>>>(pH0, W1, pHA, NNODES, 16, 256, as1, ad1, 4);
    convW_kernel<<<(256 * 256 + 255) / 256, 256>>>(W2, pW2hi, pW2lo, 256, 256);
    convW_kernel<<<(64 * 256 + 255) / 256, 256>>>(W3, pW3hi, pW3lo, 256, 64);
    scan_blocks<<<SCAN_NBLK, 1024>>>();
    scan_sums<<<1, 64>>>();
    scan_add<<<SCAN_NBLK - 1, 1024>>>();
    scatter_kernel<<<(NEDGES + 255) / 256, 256>>>(ei);

    gat_agg_smem<4, 256, true><<<NGRAPHS, 512, SM_BIG>>>(pHA, b1, pHB);

    convA_kernel<<<(nA2 + 255) / 256, 256>>>(pHB, nA2);
    mma_gemm_att<<<dim3(gridM, 4), 128, SM_MMA>>>(pAhi, pAlo, pW2hi, pW2lo, pHA,
                                                  NNODES, 256, 256, as2, ad2, 4);
    gat_agg_smem<4, 256, true><<<NGRAPHS, 512, SM_BIG>>>(pHA, b2, pHB);

    convA_kernel<<<(nA2 + 255) / 256, 256>>>(pHB, nA2);
    mma_gemm_att<<<dim3(gridM, 1), 128, SM_MMA>>>(pAhi, pAlo, pW3hi, pW3lo, pHA,
                                                  NNODES, 256, 64, as3, ad3, 1);
    gat_agg_smem<1, 64, false><<<NGRAPHS, 512, SM_SMALL>>>(pHA, b3, pHB);

    pool_kernel<<<NGRAPHS, 64>>>(pHB, ginput);
    head_kernel<<<NGRAPHS, 128>>>(bn_g, bn_b, bn_m, bn_v, Wd1, bd1, Wd2, bd2, Wo, bo, out);
}